// round 11
// baseline (speedup 1.0000x reference)
#include <cuda_runtime.h>

// NT-Xent loss. inp: (C=8, V=2, B=4096, D=512) fp32.
// Block per 8 b's (256 thr). 2-stage cp.async ring (32KB stages), ONE
// __syncthreads per tile. Per tile: per-lane 8x8 Gram tile via f32x2 FFMA2
// (i-paired accs, hoisted A-packs), 4-stage folded butterfly, folded ssv.
// All LSE epilogues deferred: warp t handles tile t in-warp (8 warps, 8 tiles).
// Deterministic ticket finish. 98KB dynamic smem -> 2 CTAs/SM.

static constexpr int      kB      = 4096;
static constexpr int      kIter   = 8;
static constexpr int      kGrid   = kB / kIter;        // 512
static constexpr unsigned FULL    = 0xffffffffu;
static constexpr int      kTileF4 = 16 * 128;          // float4 per stage
static constexpr int      kRingB  = 2 * kTileF4 * 16;  // 64 KB
static constexpr int      kPartB  = kIter * 8 * 128 * 4;  // 32 KB
static constexpr int      kOddB   = kIter * 8 * 8 * 4;    // 2 KB
static constexpr int      kSmem   = kRingB + kPartB + kOddB;  // 98 KB

__device__ float    g_partials[kGrid];
__device__ unsigned g_ticket;   // zero-init; reset by last CTA every launch

__device__ __forceinline__ float elem(const float4& v, int d) {
    return d == 0 ? v.x : d == 1 ? v.y : d == 2 ? v.z : v.w;
}
__device__ __forceinline__ unsigned long long pack2(float lo, float hi) {
    unsigned long long r;
    asm("mov.b64 %0, {%1, %2};" : "=l"(r) : "f"(lo), "f"(hi));
    return r;
}
__device__ __forceinline__ void unpack2(unsigned long long v, float& lo, float& hi) {
    asm("mov.b64 {%0, %1}, %2;" : "=f"(lo), "=f"(hi) : "l"(v));
}
__device__ __forceinline__ void ffma2(unsigned long long& acc,
                                      unsigned long long a, unsigned long long b) {
    asm("fma.rn.f32x2 %0, %1, %2, %0;" : "+l"(acc) : "l"(a), "l"(b));
}

__global__ void __launch_bounds__(256, 2)
ntxent(const float* __restrict__ inp, float* __restrict__ out)
{
    extern __shared__ char dyn[];
    float4* Xs       = reinterpret_cast<float4*>(dyn);                  // [2][16][128]
    float*  sPartAll = reinterpret_cast<float*>(dyn + kRingB);          // [8][8][128]
    float*  sOddAll  = reinterpret_cast<float*>(dyn + kRingB + kPartB); // [8][8][8]
    __shared__ float    snorm[8][16];
    __shared__ float    sLossW[8];
    __shared__ float    sred[8];
    __shared__ unsigned sFlag;

    const int tid   = threadIdx.x;
    const int w     = tid >> 5;
    const int lane  = tid & 31;
    const int h     = lane >> 4;        // col half: k in [8h, 8h+8)
    const int L4    = lane & 15;
    const int chunk = w * 16 + L4;      // this lane's float4 d-chunk

    // cp.async assignment: thread t copies row = t>>4, chunks (t&15)+16m
    const int row = tid >> 4;
    const int c16 = tid & 15;
    const long long b0 = (long long)blockIdx.x * kIter;
    const char* gbase = (const char*)(inp + ((size_t)row * kB + b0) * 512) + c16 * 16;
    const unsigned sbase = (unsigned)__cvta_generic_to_shared(&Xs[row * 128 + c16]);

    auto issue = [&](int it) {
        const char*    g = gbase + (size_t)it * 2048;          // +512 floats per b
        const unsigned s = sbase + (it & 1) * (kTileF4 * 16);
        #pragma unroll
        for (int m = 0; m < 8; m++)
            asm volatile("cp.async.cg.shared.global [%0], [%1], 16;"
                         :: "r"(s + m * 256), "l"(g + m * 256));
        asm volatile("cp.async.commit_group;" ::: "memory");
    };

    issue(0);

    #pragma unroll 2
    for (int it = 0; it < kIter; it++) {
        asm volatile("cp.async.wait_group 0;" ::: "memory");
        __syncthreads();                      // single barrier per tile
        if (it < kIter - 1) issue(it + 1);    // target buf consumed at it-1: safe

        const float4* X = Xs + (it & 1) * kTileF4;

        // ---- A pairs packed once: ap[i2*4+d] = (A[2i2].d, A[2i2+1].d) ----
        unsigned long long ap[16];
        #pragma unroll
        for (int i2 = 0; i2 < 4; i2++) {
            const float4 a0 = X[(4 * i2)     * 128 + chunk];   // row of anchor 2i2
            const float4 a1 = X[(4 * i2 + 2) * 128 + chunk];   // row of anchor 2i2+1
            ap[i2 * 4 + 0] = pack2(a0.x, a1.x);
            ap[i2 * 4 + 1] = pack2(a0.y, a1.y);
            ap[i2 * 4 + 2] = pack2(a0.z, a1.z);
            ap[i2 * 4 + 3] = pack2(a0.w, a1.w);
        }

        // ---- per-lane Gram tile: acc2[i2*8+c] = (G[2i2][8h+c], G[2i2+1][8h+c]) ----
        unsigned long long acc2[32];
        #pragma unroll
        for (int q = 0; q < 32; q++) acc2[q] = 0ull;
        float ssv[4] = {0.f, 0.f, 0.f, 0.f};

        #pragma unroll
        for (int jg = 0; jg < 2; jg++) {
            float4 Cv[4];
            #pragma unroll
            for (int jj = 0; jj < 4; jj++)
                Cv[jj] = X[(8 * h + 4 * jg + jj) * 128 + chunk];
            #pragma unroll
            for (int o = 0; o < 2; o++) {     // odd rows: jj = 2o+1
                const float4 x = Cv[2 * o + 1];
                float s = ssv[jg * 2 + o];
                s = fmaf(x.x, x.x, fmaf(x.y, x.y, fmaf(x.z, x.z, fmaf(x.w, x.w, s))));
                ssv[jg * 2 + o] = s;
            }
            #pragma unroll
            for (int d = 0; d < 4; d++)
                #pragma unroll
                for (int jj = 0; jj < 4; jj++) {
                    const float cd = elem(Cv[jj], d);
                    const unsigned long long cq = pack2(cd, cd);
                    #pragma unroll
                    for (int i2 = 0; i2 < 4; i2++)
                        ffma2(acc2[i2 * 8 + jg * 4 + jj], ap[i2 * 4 + d], cq);
                }
        }

        // ---- unpack (register-pair renames) ----
        float a[64];
        #pragma unroll
        for (int i2 = 0; i2 < 4; i2++)
            #pragma unroll
            for (int c = 0; c < 8; c++)
                unpack2(acc2[i2 * 8 + c], a[(2 * i2) * 8 + c], a[(2 * i2 + 1) * 8 + c]);

        // ---- folded butterfly over 16 chunk-lanes (bits 3..0) ----
        #pragma unroll
        for (int s = 0; s < 4; s++) {
            const int  off = 8 >> s;
            const int  n   = 32 >> s;
            const bool hi  = (lane & off) != 0;
            #pragma unroll
            for (int m = 0; m < n; m++) {
                const float mine = hi ? a[m + n] : a[m];
                const float send = hi ? a[m]     : a[m + n];
                a[m] = mine + __shfl_xor_sync(FULL, send, off);
            }
        }
        // lane owns flat64 = 4*L4 + m: i = L4>>1, k = (L4&1)*4 + 8h + m
        {
            const int i  = L4 >> 1;
            const int kb = (L4 & 1) * 4 + 8 * h;
            *reinterpret_cast<float4*>(
                &sPartAll[(it * 8 + w) * 128 + i * 16 + kb]) =
                make_float4(a[0], a[1], a[2], a[3]);
        }

        // ---- folded ssv: q = 2*bit3(L4) + bit2(L4), writers L4&3==0 ----
        {
            bool hi = (lane & 8) != 0;
            #pragma unroll
            for (int m = 0; m < 2; m++) {
                const float mine = hi ? ssv[m + 2] : ssv[m];
                const float send = hi ? ssv[m]     : ssv[m + 2];
                ssv[m] = mine + __shfl_xor_sync(FULL, send, 8);
            }
            hi = (lane & 4) != 0;
            {
                const float mine = hi ? ssv[1] : ssv[0];
                const float send = hi ? ssv[0] : ssv[1];
                ssv[0] = mine + __shfl_xor_sync(FULL, send, 4);
            }
            ssv[0] += __shfl_xor_sync(FULL, ssv[0], 2);
            ssv[0] += __shfl_xor_sync(FULL, ssv[0], 1);
            if ((L4 & 3) == 0) {
                const int q = ((L4 >> 3) & 1) * 2 + ((L4 >> 2) & 1);
                sOddAll[(it * 8 + w) * 8 + q + 4 * h] = ssv[0];  // row 2*(q+4h)+1
            }
        }
    }
    __syncthreads();

    // ---- deferred epilogues: warp t handles tile t, fully in-warp ----
    {
        const int i  = lane >> 2;
        const int kb = 4 * (lane & 3);
        float4 acc = make_float4(0.f, 0.f, 0.f, 0.f);
        #pragma unroll
        for (int ww = 0; ww < 8; ww++) {
            const float4 p = *reinterpret_cast<const float4*>(
                &sPartAll[(w * 8 + ww) * 128 + i * 16 + kb]);
            acc.x += p.x; acc.y += p.y; acc.z += p.z; acc.w += p.w;
        }
        float a4[4] = {acc.x, acc.y, acc.z, acc.w};

        if (lane < 8) {
            float so = 0.f;
            #pragma unroll
            for (int ww = 0; ww < 8; ww++) so += sOddAll[(w * 8 + ww) * 8 + lane];
            snorm[w][2 * lane + 1] = so;
        }
        #pragma unroll
        for (int m = 0; m < 4; m++)                 // even norms = Gram diag
            if (kb + m == 2 * i) snorm[w][2 * i] = a4[m];
        __syncwarp();

        const float inva = 1.0f / fmaxf(sqrtf(snorm[w][2 * i]), 1e-12f);
        float sim[4];
        bool  val[4];
        float mx = -3.0e38f;
        #pragma unroll
        for (int m = 0; m < 4; m++) {
            const int   k    = kb + m;
            const float invk = 1.0f / fmaxf(sqrtf(snorm[w][k]), 1e-12f);
            sim[m] = a4[m] * inva * invk * 10.0f;
            val[m] = ((k >> 1) != i) || (k == 2 * i + 1);
            if (val[m]) mx = fmaxf(mx, sim[m]);
        }
        mx = fmaxf(mx, __shfl_xor_sync(FULL, mx, 1));
        mx = fmaxf(mx, __shfl_xor_sync(FULL, mx, 2));
        float sum = 0.f;
        #pragma unroll
        for (int m = 0; m < 4; m++)
            if (val[m]) sum += __expf(sim[m] - mx);
        sum += __shfl_xor_sync(FULL, sum, 1);
        sum += __shfl_xor_sync(FULL, sum, 2);

        float contrib = 0.f;
        #pragma unroll
        for (int m = 0; m < 4; m++)
            if (kb + m == 2 * i + 1)                // this sim is the positive
                contrib = (mx + __logf(sum)) - sim[m];
        #pragma unroll
        for (int off = 16; off > 0; off >>= 1)
            contrib += __shfl_xor_sync(FULL, contrib, off);
        if (lane == 0) sLossW[w] = contrib;
    }
    __syncthreads();

    // ---- deterministic fused finish ----
    if (tid == 0) {
        float t = 0.f;
        #pragma unroll
        for (int i = 0; i < 8; i++) t += sLossW[i];
        g_partials[blockIdx.x] = t;
        __threadfence();
        const unsigned tk = atomicAdd(&g_ticket, 1u);
        sFlag = (tk == kGrid - 1) ? 1u : 0u;
    }
    __syncthreads();
    if (sFlag) {
        float s = 0.f;
        #pragma unroll
        for (int m = 0; m < kGrid / 256; m++)
            s += __ldcg(&g_partials[tid + m * 256]);   // fixed order
        #pragma unroll
        for (int off = 16; off > 0; off >>= 1)
            s += __shfl_xor_sync(FULL, s, off);
        if (lane == 0) sred[w] = s;
        __syncthreads();
        if (tid == 0) {
            float tot = 0.f;
            #pragma unroll
            for (int i = 0; i < 8; i++) tot += sred[i];
            out[0] = tot * (1.0f / (8.0f * 4096.0f));
            g_ticket = 0u;   // reset for next graph replay
        }
    }
}

extern "C" void kernel_launch(void* const* d_in, const int* in_sizes, int n_in,
                              void* d_out, int out_size) {
    (void)in_sizes; (void)n_in; (void)out_size;
    const float* inp = (const float*)d_in[0];
    cudaFuncSetAttribute(ntxent, cudaFuncAttributeMaxDynamicSharedMemorySize, kSmem);
    ntxent<<<kGrid, 256, kSmem>>>(inp, (float*)d_out);
}

// round 12
// speedup vs baseline: 1.1304x; 1.1304x over previous
#include <cuda_runtime.h>

// NT-Xent loss. inp: (C=8, V=2, B=4096, D=512) fp32.
// Block per 4 b's (256 thr). 2-stage cp.async ring (32KB stages), ONE
// __syncthreads per tile, prefetch distance 1. Per tile: per-lane 8x8
// scalar-FMA Gram tile (chunk = w*16 + (lane&15), lane bit4 = col half),
// 4-stage folded butterfly, folded ssv reduce. LSE epilogues deferred
// (warp t handles tile t in-warp). Deterministic ticket finish.
// R10 structure (43.0us) + folded ssv only; f32x2 reverted (R11 regression).

static constexpr int      kB      = 4096;
static constexpr int      kIter   = 4;
static constexpr int      kGrid   = kB / kIter;        // 1024
static constexpr unsigned FULL    = 0xffffffffu;
static constexpr int      kTileF4 = 16 * 128;          // float4 per stage
static constexpr int      kRingB  = 2 * kTileF4 * 16;  // 64 KB
static constexpr int      kPartB  = kIter * 8 * 128 * 4;  // 16 KB
static constexpr int      kOddB   = kIter * 8 * 8 * 4;    // 1 KB
static constexpr int      kSmem   = kRingB + kPartB + kOddB;  // 81 KB

__device__ float    g_partials[kGrid];
__device__ unsigned g_ticket;   // zero-init; reset by last CTA every launch

__device__ __forceinline__ float elem(const float4& v, int d) {
    return d == 0 ? v.x : d == 1 ? v.y : d == 2 ? v.z : v.w;
}

__global__ void __launch_bounds__(256, 2)
ntxent(const float* __restrict__ inp, float* __restrict__ out)
{
    extern __shared__ char dyn[];
    float4* Xs       = reinterpret_cast<float4*>(dyn);                  // [2][16][128]
    float*  sPartAll = reinterpret_cast<float*>(dyn + kRingB);          // [4][8][128]
    float*  sOddAll  = reinterpret_cast<float*>(dyn + kRingB + kPartB); // [4][8][8]
    __shared__ float    snorm[4][16];
    __shared__ float    sLossW[4];
    __shared__ float    sred[8];
    __shared__ unsigned sFlag;

    const int tid   = threadIdx.x;
    const int w     = tid >> 5;
    const int lane  = tid & 31;
    const int h     = lane >> 4;        // col half: k in [8h, 8h+8)
    const int L4    = lane & 15;
    const int chunk = w * 16 + L4;      // this lane's float4 d-chunk

    // cp.async assignment: thread t copies row = t>>4, chunks (t&15)+16m
    const int row = tid >> 4;
    const int c16 = tid & 15;
    const long long b0 = (long long)blockIdx.x * kIter;
    const char* gbase = (const char*)(inp + ((size_t)row * kB + b0) * 512) + c16 * 16;
    const unsigned sbase = (unsigned)__cvta_generic_to_shared(&Xs[row * 128 + c16]);

    auto issue = [&](int it) {
        const char*    g = gbase + (size_t)it * 2048;          // +512 floats per b
        const unsigned s = sbase + (it & 1) * (kTileF4 * 16);
        #pragma unroll
        for (int m = 0; m < 8; m++)
            asm volatile("cp.async.cg.shared.global [%0], [%1], 16;"
                         :: "r"(s + m * 256), "l"(g + m * 256));
        asm volatile("cp.async.commit_group;" ::: "memory");
    };

    issue(0);

    #pragma unroll
    for (int it = 0; it < kIter; it++) {
        asm volatile("cp.async.wait_group 0;" ::: "memory");
        __syncthreads();                      // single barrier per tile
        if (it + 1 < kIter) issue(it + 1);    // target buf consumed at it-1: safe

        const float4* X = Xs + (it & 1) * kTileF4;

        // ---- per-lane 8x8 Gram tile + odd-row sumsq ----
        float4 A[8];
        #pragma unroll
        for (int i = 0; i < 8; i++) A[i] = X[(2 * i) * 128 + chunk];

        float a[64];
        #pragma unroll
        for (int q = 0; q < 64; q++) a[q] = 0.f;
        float ssv[4] = {0.f, 0.f, 0.f, 0.f};

        #pragma unroll
        for (int jg = 0; jg < 2; jg++) {
            float4 Cv[4];
            #pragma unroll
            for (int jj = 0; jj < 4; jj++)
                Cv[jj] = X[(8 * h + jg * 4 + jj) * 128 + chunk];
            #pragma unroll
            for (int o = 0; o < 2; o++) {     // odd rows j = jg*4 + {1,3}
                const float4 x = Cv[2 * o + 1];
                float s = ssv[jg * 2 + o];
                s = fmaf(x.x, x.x, fmaf(x.y, x.y, fmaf(x.z, x.z, fmaf(x.w, x.w, s))));
                ssv[jg * 2 + o] = s;
            }
            #pragma unroll
            for (int d = 0; d < 4; d++)
                #pragma unroll
                for (int i = 0; i < 8; i++) {
                    const float av = elem(A[i], d);
                    #pragma unroll
                    for (int jj = 0; jj < 4; jj++)
                        a[i * 8 + jg * 4 + jj] =
                            fmaf(av, elem(Cv[jj], d), a[i * 8 + jg * 4 + jj]);
                }
        }

        // ---- folded butterfly over 16 chunk-lanes (bits 3..0) ----
        #pragma unroll
        for (int s = 0; s < 4; s++) {
            const int  off = 8 >> s;
            const int  n   = 32 >> s;
            const bool hi  = (lane & off) != 0;
            #pragma unroll
            for (int m = 0; m < n; m++) {
                const float mine = hi ? a[m + n] : a[m];
                const float send = hi ? a[m]     : a[m + n];
                a[m] = mine + __shfl_xor_sync(FULL, send, off);
            }
        }
        // lane owns flat64 = 4*L4 + m: i = L4>>1, k = (L4&1)*4 + 8h + m
        {
            const int i  = L4 >> 1;
            const int kb = (L4 & 1) * 4 + 8 * h;
            *reinterpret_cast<float4*>(
                &sPartAll[(it * 8 + w) * 128 + i * 16 + kb]) =
                make_float4(a[0], a[1], a[2], a[3]);
        }

        // ---- folded ssv: q = 2*bit3(L4) + bit2(L4), writers L4&3==0 ----
        {
            bool hi = (lane & 8) != 0;
            #pragma unroll
            for (int m = 0; m < 2; m++) {
                const float mine = hi ? ssv[m + 2] : ssv[m];
                const float send = hi ? ssv[m]     : ssv[m + 2];
                ssv[m] = mine + __shfl_xor_sync(FULL, send, 8);
            }
            hi = (lane & 4) != 0;
            {
                const float mine = hi ? ssv[1] : ssv[0];
                const float send = hi ? ssv[0] : ssv[1];
                ssv[0] = mine + __shfl_xor_sync(FULL, send, 4);
            }
            ssv[0] += __shfl_xor_sync(FULL, ssv[0], 2);
            ssv[0] += __shfl_xor_sync(FULL, ssv[0], 1);
            if ((L4 & 3) == 0) {
                const int q = ((L4 >> 3) & 1) * 2 + ((L4 >> 2) & 1);
                sOddAll[(it * 8 + w) * 8 + q + 4 * h] = ssv[0];  // row 2*(q+4h)+1
            }
        }
    }
    __syncthreads();

    // ---- deferred epilogues: warp t handles tile t, fully in-warp ----
    if (w < 4) {
        const int i  = lane >> 2;
        const int kb = 4 * (lane & 3);
        float4 acc = make_float4(0.f, 0.f, 0.f, 0.f);
        #pragma unroll
        for (int ww = 0; ww < 8; ww++) {
            const float4 p = *reinterpret_cast<const float4*>(
                &sPartAll[(w * 8 + ww) * 128 + i * 16 + kb]);
            acc.x += p.x; acc.y += p.y; acc.z += p.z; acc.w += p.w;
        }
        float a4[4] = {acc.x, acc.y, acc.z, acc.w};

        if (lane < 8) {
            float so = 0.f;
            #pragma unroll
            for (int ww = 0; ww < 8; ww++) so += sOddAll[(w * 8 + ww) * 8 + lane];
            snorm[w][2 * lane + 1] = so;
        }
        #pragma unroll
        for (int m = 0; m < 4; m++)                 // even norms = Gram diag
            if (kb + m == 2 * i) snorm[w][2 * i] = a4[m];
        __syncwarp();

        const float inva = 1.0f / fmaxf(sqrtf(snorm[w][2 * i]), 1e-12f);
        float sim[4];
        bool  val[4];
        float mx = -3.0e38f;
        #pragma unroll
        for (int m = 0; m < 4; m++) {
            const int   k    = kb + m;
            const float invk = 1.0f / fmaxf(sqrtf(snorm[w][k]), 1e-12f);
            sim[m] = a4[m] * inva * invk * 10.0f;
            val[m] = ((k >> 1) != i) || (k == 2 * i + 1);
            if (val[m]) mx = fmaxf(mx, sim[m]);
        }
        mx = fmaxf(mx, __shfl_xor_sync(FULL, mx, 1));
        mx = fmaxf(mx, __shfl_xor_sync(FULL, mx, 2));
        float sum = 0.f;
        #pragma unroll
        for (int m = 0; m < 4; m++)
            if (val[m]) sum += __expf(sim[m] - mx);
        sum += __shfl_xor_sync(FULL, sum, 1);
        sum += __shfl_xor_sync(FULL, sum, 2);

        float contrib = 0.f;
        #pragma unroll
        for (int m = 0; m < 4; m++)
            if (kb + m == 2 * i + 1)                // this sim is the positive
                contrib = (mx + __logf(sum)) - sim[m];
        #pragma unroll
        for (int off = 16; off > 0; off >>= 1)
            contrib += __shfl_xor_sync(FULL, contrib, off);
        if (lane == 0) sLossW[w] = contrib;
    }
    __syncthreads();

    // ---- deterministic fused finish ----
    if (tid == 0) {
        g_partials[blockIdx.x] = sLossW[0] + sLossW[1] + sLossW[2] + sLossW[3];
        __threadfence();
        const unsigned tk = atomicAdd(&g_ticket, 1u);
        sFlag = (tk == kGrid - 1) ? 1u : 0u;
    }
    __syncthreads();
    if (sFlag) {
        float s = 0.f;
        #pragma unroll
        for (int m = 0; m < kGrid / 256; m++)
            s += __ldcg(&g_partials[tid + m * 256]);   // fixed order
        #pragma unroll
        for (int off = 16; off > 0; off >>= 1)
            s += __shfl_xor_sync(FULL, s, off);
        if (lane == 0) sred[w] = s;
        __syncthreads();
        if (tid == 0) {
            float tot = 0.f;
            #pragma unroll
            for (int i = 0; i < 8; i++) tot += sred[i];
            out[0] = tot * (1.0f / (8.0f * 4096.0f));
            g_ticket = 0u;   // reset for next graph replay
        }
    }
}

extern "C" void kernel_launch(void* const* d_in, const int* in_sizes, int n_in,
                              void* d_out, int out_size) {
    (void)in_sizes; (void)n_in; (void)out_size;
    const float* inp = (const float*)d_in[0];
    cudaFuncSetAttribute(ntxent, cudaFuncAttributeMaxDynamicSharedMemorySize, kSmem);
    ntxent<<<kGrid, 256, kSmem>>>(inp, (float*)d_out);
}

// round 13
// speedup vs baseline: 1.2335x; 1.0912x over previous
#include <cuda_runtime.h>

// NT-Xent loss. inp: (C=8, V=2, B=4096, D=512) fp32.
// Block per 4 b's (256 thr). 2-stage cp.async ring (32KB stages), ONE
// __syncthreads per tile, prefetch distance 1. Per tile: lane = (g, c8),
// g = lane>>3 owns col quarter [4g,4g+4), c8 = lane&7 indexes chunks
// (2 chunks per lane: w*16 + c8 + 8p). 8x4 Gram tile per lane (32 accs),
// 3-stage folded butterfly (bits 2..0) -> lane owns G[c8][4g+m].
// ssv (2 odd cols per lane) allreduced with 6 shfl. LSE epilogues deferred
// (warp t handles tile t in-warp, R10-validated). Deterministic ticket finish.

static constexpr int      kB      = 4096;
static constexpr int      kIter   = 4;
static constexpr int      kGrid   = kB / kIter;        // 1024
static constexpr unsigned FULL    = 0xffffffffu;
static constexpr int      kTileF4 = 16 * 128;          // float4 per stage
static constexpr int      kRingB  = 2 * kTileF4 * 16;  // 64 KB
static constexpr int      kPartB  = kIter * 8 * 128 * 4;  // 16 KB
static constexpr int      kOddB   = kIter * 8 * 8 * 4;    // 1 KB
static constexpr int      kSmem   = kRingB + kPartB + kOddB;  // 81 KB

__device__ float    g_partials[kGrid];
__device__ unsigned g_ticket;   // zero-init; reset by last CTA every launch

__device__ __forceinline__ float elem(const float4& v, int d) {
    return d == 0 ? v.x : d == 1 ? v.y : d == 2 ? v.z : v.w;
}

__global__ void __launch_bounds__(256, 2)
ntxent(const float* __restrict__ inp, float* __restrict__ out)
{
    extern __shared__ char dyn[];
    float4* Xs       = reinterpret_cast<float4*>(dyn);                  // [2][16][128]
    float*  sPartAll = reinterpret_cast<float*>(dyn + kRingB);          // [4][8][128]
    float*  sOddAll  = reinterpret_cast<float*>(dyn + kRingB + kPartB); // [4][8][8]
    __shared__ float    snorm[4][16];
    __shared__ float    sLossW[4];
    __shared__ float    sred[8];
    __shared__ unsigned sFlag;

    const int tid  = threadIdx.x;
    const int w    = tid >> 5;
    const int lane = tid & 31;
    const int g    = lane >> 3;         // col quarter: cols [4g, 4g+4)
    const int c8   = lane & 7;          // chunk index within warp D-slice

    // cp.async assignment: thread t copies row = t>>4, chunks (t&15)+16m
    const int row = tid >> 4;
    const int c16 = tid & 15;
    const long long b0 = (long long)blockIdx.x * kIter;
    const char* gbase = (const char*)(inp + ((size_t)row * kB + b0) * 512) + c16 * 16;
    const unsigned sbase = (unsigned)__cvta_generic_to_shared(&Xs[row * 128 + c16]);

    auto issue = [&](int it) {
        const char*    g2 = gbase + (size_t)it * 2048;         // +512 floats per b
        const unsigned s  = sbase + (it & 1) * (kTileF4 * 16);
        #pragma unroll
        for (int m = 0; m < 8; m++)
            asm volatile("cp.async.cg.shared.global [%0], [%1], 16;"
                         :: "r"(s + m * 256), "l"(g2 + m * 256));
        asm volatile("cp.async.commit_group;" ::: "memory");
    };

    issue(0);

    #pragma unroll
    for (int it = 0; it < kIter; it++) {
        asm volatile("cp.async.wait_group 0;" ::: "memory");
        __syncthreads();                      // single barrier per tile
        if (it + 1 < kIter) issue(it + 1);    // target buf consumed at it-1: safe

        const float4* X = Xs + (it & 1) * kTileF4;

        // ---- per-lane 8x4 Gram tile over 2 chunks + odd-col sumsq ----
        float a[32];
        #pragma unroll
        for (int q = 0; q < 32; q++) a[q] = 0.f;
        float ssv[2] = {0.f, 0.f};

        #pragma unroll
        for (int p = 0; p < 2; p++) {
            const int chunk = w * 16 + c8 + 8 * p;
            float4 Cv[4];
            #pragma unroll
            for (int jj = 0; jj < 4; jj++)
                Cv[jj] = X[(4 * g + jj) * 128 + chunk];
            #pragma unroll
            for (int o = 0; o < 2; o++) {     // odd rows 4g+1, 4g+3
                const float4 x = Cv[2 * o + 1];
                float s = ssv[o];
                s = fmaf(x.x, x.x, fmaf(x.y, x.y, fmaf(x.z, x.z, fmaf(x.w, x.w, s))));
                ssv[o] = s;
            }
            float4 A[8];
            #pragma unroll
            for (int i = 0; i < 8; i++) A[i] = X[(2 * i) * 128 + chunk];
            #pragma unroll
            for (int d = 0; d < 4; d++)
                #pragma unroll
                for (int i = 0; i < 8; i++) {
                    const float av = elem(A[i], d);
                    #pragma unroll
                    for (int jj = 0; jj < 4; jj++)
                        a[i * 4 + jj] = fmaf(av, elem(Cv[jj], d), a[i * 4 + jj]);
                }
        }

        // ---- folded butterfly over 8 chunk-lanes (bits 2..0) ----
        #pragma unroll
        for (int s = 0; s < 3; s++) {
            const int  off = 4 >> s;
            const int  n   = 16 >> s;
            const bool hi  = (lane & off) != 0;
            #pragma unroll
            for (int m = 0; m < n; m++) {
                const float mine = hi ? a[m + n] : a[m];
                const float send = hi ? a[m]     : a[m + n];
                a[m] = mine + __shfl_xor_sync(FULL, send, off);
            }
        }
        // lane owns flat32 = 4*c8 + m: i = c8, col = 4g + m
        *reinterpret_cast<float4*>(
            &sPartAll[(it * 8 + w) * 128 + c8 * 16 + 4 * g]) =
            make_float4(a[0], a[1], a[2], a[3]);

        // ---- ssv allreduce over 8 chunk-lanes; writers c8 == 0 ----
        #pragma unroll
        for (int off = 4; off > 0; off >>= 1) {
            ssv[0] += __shfl_xor_sync(FULL, ssv[0], off);
            ssv[1] += __shfl_xor_sync(FULL, ssv[1], off);
        }
        if (c8 == 0) {
            sOddAll[(it * 8 + w) * 8 + 2 * g]     = ssv[0];   // row 4g+1
            sOddAll[(it * 8 + w) * 8 + 2 * g + 1] = ssv[1];   // row 4g+3
        }
    }
    __syncthreads();

    // ---- deferred epilogues: warp t handles tile t, fully in-warp ----
    if (w < 4) {
        const int i  = lane >> 2;
        const int kb = 4 * (lane & 3);
        float4 acc = make_float4(0.f, 0.f, 0.f, 0.f);
        #pragma unroll
        for (int ww = 0; ww < 8; ww++) {
            const float4 p = *reinterpret_cast<const float4*>(
                &sPartAll[(w * 8 + ww) * 128 + i * 16 + kb]);
            acc.x += p.x; acc.y += p.y; acc.z += p.z; acc.w += p.w;
        }
        float a4[4] = {acc.x, acc.y, acc.z, acc.w};

        if (lane < 8) {
            float so = 0.f;
            #pragma unroll
            for (int ww = 0; ww < 8; ww++) so += sOddAll[(w * 8 + ww) * 8 + lane];
            snorm[w][2 * lane + 1] = so;
        }
        #pragma unroll
        for (int m = 0; m < 4; m++)                 // even norms = Gram diag
            if (kb + m == 2 * i) snorm[w][2 * i] = a4[m];
        __syncwarp();

        const float inva = 1.0f / fmaxf(sqrtf(snorm[w][2 * i]), 1e-12f);
        float sim[4];
        bool  val[4];
        float mx = -3.0e38f;
        #pragma unroll
        for (int m = 0; m < 4; m++) {
            const int   k    = kb + m;
            const float invk = 1.0f / fmaxf(sqrtf(snorm[w][k]), 1e-12f);
            sim[m] = a4[m] * inva * invk * 10.0f;
            val[m] = ((k >> 1) != i) || (k == 2 * i + 1);
            if (val[m]) mx = fmaxf(mx, sim[m]);
        }
        mx = fmaxf(mx, __shfl_xor_sync(FULL, mx, 1));
        mx = fmaxf(mx, __shfl_xor_sync(FULL, mx, 2));
        float sum = 0.f;
        #pragma unroll
        for (int m = 0; m < 4; m++)
            if (val[m]) sum += __expf(sim[m] - mx);
        sum += __shfl_xor_sync(FULL, sum, 1);
        sum += __shfl_xor_sync(FULL, sum, 2);

        float contrib = 0.f;
        #pragma unroll
        for (int m = 0; m < 4; m++)
            if (kb + m == 2 * i + 1)                // this sim is the positive
                contrib = (mx + __logf(sum)) - sim[m];
        #pragma unroll
        for (int off = 16; off > 0; off >>= 1)
            contrib += __shfl_xor_sync(FULL, contrib, off);
        if (lane == 0) sLossW[w] = contrib;
    }
    __syncthreads();

    // ---- deterministic fused finish ----
    if (tid == 0) {
        g_partials[blockIdx.x] = sLossW[0] + sLossW[1] + sLossW[2] + sLossW[3];
        __threadfence();
        const unsigned tk = atomicAdd(&g_ticket, 1u);
        sFlag = (tk == kGrid - 1) ? 1u : 0u;
    }
    __syncthreads();
    if (sFlag) {
        float s = 0.f;
        #pragma unroll
        for (int m = 0; m < kGrid / 256; m++)
            s += __ldcg(&g_partials[tid + m * 256]);   // fixed order
        #pragma unroll
        for (int off = 16; off > 0; off >>= 1)
            s += __shfl_xor_sync(FULL, s, off);
        if (lane == 0) sred[w] = s;
        __syncthreads();
        if (tid == 0) {
            float tot = 0.f;
            #pragma unroll
            for (int i = 0; i < 8; i++) tot += sred[i];
            out[0] = tot * (1.0f / (8.0f * 4096.0f));
            g_ticket = 0u;   // reset for next graph replay
        }
    }
}

extern "C" void kernel_launch(void* const* d_in, const int* in_sizes, int n_in,
                              void* d_out, int out_size) {
    (void)in_sizes; (void)n_in; (void)out_size;
    const float* inp = (const float*)d_in[0];
    cudaFuncSetAttribute(ntxent, cudaFuncAttributeMaxDynamicSharedMemorySize, kSmem);
    ntxent<<<kGrid, 256, kSmem>>>(inp, (float*)d_out);
}

// round 15
// speedup vs baseline: 1.2990x; 1.0531x over previous
#include <cuda_runtime.h>

// NT-Xent loss. inp: (C=8, V=2, B=4096, D=512) fp32.
// Block per 4 b's (256 thr). WARP-AUTONOMOUS mainloop: warp w stages and
// reads ONLY its own d-slice (chunks w*16..w*16+15, 4KB/stage), 2-stage
// private ring, cp.async.wait_group + __syncwarp only — NO __syncthreads
// in the mainloop. Per tile: lane = (g, c8) 8x4 Gram tile (R13-validated),
// 3-stage folded butterfly -> lane owns G[c8][4g+m], ssv allreduce.
// One block barrier, then deferred in-warp LSE epilogues + ticket finish.

static constexpr int      kB      = 4096;
static constexpr int      kIter   = 4;
static constexpr int      kGrid   = kB / kIter;        // 1024
static constexpr unsigned FULL    = 0xffffffffu;
static constexpr int      kTileF4 = 16 * 128;          // float4 per stage (all warps)
static constexpr int      kRingB  = 2 * kTileF4 * 16;  // 64 KB
static constexpr int      kPartB  = kIter * 8 * 128 * 4;  // 16 KB
static constexpr int      kOddB   = kIter * 8 * 8 * 4;    // 1 KB
static constexpr int      kSmem   = kRingB + kPartB + kOddB;  // 81 KB

__device__ float    g_partials[kGrid];
__device__ unsigned g_ticket;   // zero-init; reset by last CTA every launch

__device__ __forceinline__ float elem(const float4& v, int d) {
    return d == 0 ? v.x : d == 1 ? v.y : d == 2 ? v.z : v.w;
}

__global__ void __launch_bounds__(256, 2)
ntxent(const float* __restrict__ inp, float* __restrict__ out)
{
    extern __shared__ char dyn[];
    float4* Xs       = reinterpret_cast<float4*>(dyn);                  // [2][16][128]
    float*  sPartAll = reinterpret_cast<float*>(dyn + kRingB);          // [4][8][128]
    float*  sOddAll  = reinterpret_cast<float*>(dyn + kRingB + kPartB); // [4][8][8]
    __shared__ float    snorm[4][16];
    __shared__ float    sLossW[4];
    __shared__ float    sred[8];
    __shared__ unsigned sFlag;

    const int tid  = threadIdx.x;
    const int w    = tid >> 5;
    const int lane = tid & 31;
    const int g    = lane >> 3;         // col quarter: cols [4g, 4g+4)
    const int c8   = lane & 7;          // chunk index within warp D-slice

    // ---- warp-private copy assignment: lane (r2, c) copies rows 2m+r2,
    //      chunk w*16+cc of this warp's slice (half-warp = 256B contiguous) ----
    const int r2 = lane >> 4;           // row parity
    const int cc = lane & 15;           // chunk within slice
    const long long b0 = (long long)blockIdx.x * kIter;
    // byte addr of (row, b, chunk): (row*4096 + b)*2048 + (w*16+cc)*16
    const char* gsrc = (const char*)inp + ((size_t)r2 * kB + b0) * 2048
                     + (size_t)(w * 16 + cc) * 16;
    const unsigned sdl = (unsigned)__cvta_generic_to_shared(Xs)
                       + r2 * 2048 + (w * 16 + cc) * 16;

    auto issue = [&](int it) {
        const char*    gp = gsrc + (size_t)it * 2048;       // +1 b
        const unsigned sp = sdl + (it & 1) * 32768;
        #pragma unroll
        for (int m = 0; m < 8; m++)                          // rows 2m + r2
            asm volatile("cp.async.cg.shared.global [%0], [%1], 16;"
                         :: "r"(sp + m * 4096), "l"(gp + (size_t)m * 16777216));
        asm volatile("cp.async.commit_group;" ::: "memory");
    };

    issue(0);
    issue(1);

    #pragma unroll
    for (int it = 0; it < kIter; it++) {
        if (it < kIter - 1) asm volatile("cp.async.wait_group 1;" ::: "memory");
        else                asm volatile("cp.async.wait_group 0;" ::: "memory");
        __syncwarp();                         // warp-local: data visible to all lanes

        const float4* X = Xs + (it & 1) * kTileF4;

        // ---- per-lane 8x4 Gram tile over 2 chunks + odd-col sumsq ----
        float a[32];
        #pragma unroll
        for (int q = 0; q < 32; q++) a[q] = 0.f;
        float ssv[2] = {0.f, 0.f};

        #pragma unroll
        for (int p = 0; p < 2; p++) {
            const int chunk = w * 16 + c8 + 8 * p;
            float4 Cv[4];
            #pragma unroll
            for (int jj = 0; jj < 4; jj++)
                Cv[jj] = X[(4 * g + jj) * 128 + chunk];
            #pragma unroll
            for (int o = 0; o < 2; o++) {     // odd rows 4g+1, 4g+3
                const float4 x = Cv[2 * o + 1];
                float s = ssv[o];
                s = fmaf(x.x, x.x, fmaf(x.y, x.y, fmaf(x.z, x.z, fmaf(x.w, x.w, s))));
                ssv[o] = s;
            }
            float4 A[8];
            #pragma unroll
            for (int i = 0; i < 8; i++) A[i] = X[(2 * i) * 128 + chunk];
            #pragma unroll
            for (int d = 0; d < 4; d++)
                #pragma unroll
                for (int i = 0; i < 8; i++) {
                    const float av = elem(A[i], d);
                    #pragma unroll
                    for (int jj = 0; jj < 4; jj++)
                        a[i * 4 + jj] = fmaf(av, elem(Cv[jj], d), a[i * 4 + jj]);
                }
        }
        __syncwarp();                         // all lanes done reading this buffer
        if (it + 2 < kIter) issue(it + 2);    // reuse buffer it&1: safe within warp

        // ---- folded butterfly over 8 chunk-lanes (bits 2..0) ----
        #pragma unroll
        for (int s = 0; s < 3; s++) {
            const int  off = 4 >> s;
            const int  n   = 16 >> s;
            const bool hi  = (lane & off) != 0;
            #pragma unroll
            for (int m = 0; m < n; m++) {
                const float mine = hi ? a[m + n] : a[m];
                const float send = hi ? a[m]     : a[m + n];
                a[m] = mine + __shfl_xor_sync(FULL, send, off);
            }
        }
        // lane owns flat32 = 4*c8 + m: i = c8, col = 4g + m
        *reinterpret_cast<float4*>(
            &sPartAll[(it * 8 + w) * 128 + c8 * 16 + 4 * g]) =
            make_float4(a[0], a[1], a[2], a[3]);

        // ---- ssv allreduce over 8 chunk-lanes; writers c8 == 0 ----
        #pragma unroll
        for (int off = 4; off > 0; off >>= 1) {
            ssv[0] += __shfl_xor_sync(FULL, ssv[0], off);
            ssv[1] += __shfl_xor_sync(FULL, ssv[1], off);
        }
        if (c8 == 0) {
            sOddAll[(it * 8 + w) * 8 + 2 * g]     = ssv[0];   // row 4g+1
            sOddAll[(it * 8 + w) * 8 + 2 * g + 1] = ssv[1];   // row 4g+3
        }
    }
    __syncthreads();   // the ONLY block barrier: all warps' partials visible

    // ---- deferred epilogues: warp t handles tile t, fully in-warp ----
    if (w < 4) {
        const int i  = lane >> 2;
        const int kb = 4 * (lane & 3);
        float4 acc = make_float4(0.f, 0.f, 0.f, 0.f);
        #pragma unroll
        for (int ww = 0; ww < 8; ww++) {
            const float4 p = *reinterpret_cast<const float4*>(
                &sPartAll[(w * 8 + ww) * 128 + i * 16 + kb]);
            acc.x += p.x; acc.y += p.y; acc.z += p.z; acc.w += p.w;
        }
        float a4[4] = {acc.x, acc.y, acc.z, acc.w};

        if (lane < 8) {
            float so = 0.f;
            #pragma unroll
            for (int ww = 0; ww < 8; ww++) so += sOddAll[(w * 8 + ww) * 8 + lane];
            snorm[w][2 * lane + 1] = so;
        }
        #pragma unroll
        for (int m = 0; m < 4; m++)                 // even norms = Gram diag
            if (kb + m == 2 * i) snorm[w][2 * i] = a4[m];
        __syncwarp();

        const float inva = 1.0f / fmaxf(sqrtf(snorm[w][2 * i]), 1e-12f);
        float sim[4];
        bool  val[4];
        float mx = -3.0e38f;
        #pragma unroll
        for (int m = 0; m < 4; m++) {
            const int   k    = kb + m;
            const float invk = 1.0f / fmaxf(sqrtf(snorm[w][k]), 1e-12f);
            sim[m] = a4[m] * inva * invk * 10.0f;
            val[m] = ((k >> 1) != i) || (k == 2 * i + 1);
            if (val[m]) mx = fmaxf(mx, sim[m]);
        }
        mx = fmaxf(mx, __shfl_xor_sync(FULL, mx, 1));
        mx = fmaxf(mx, __shfl_xor_sync(FULL, mx, 2));
        float sum = 0.f;
        #pragma unroll
        for (int m = 0; m < 4; m++)
            if (val[m]) sum += __expf(sim[m] - mx);
        sum += __shfl_xor_sync(FULL, sum, 1);
        sum += __shfl_xor_sync(FULL, sum, 2);

        float contrib = 0.f;
        #pragma unroll
        for (int m = 0; m < 4; m++)
            if (kb + m == 2 * i + 1)                // this sim is the positive
                contrib = (mx + __logf(sum)) - sim[m];
        #pragma unroll
        for (int off = 16; off > 0; off >>= 1)
            contrib += __shfl_xor_sync(FULL, contrib, off);
        if (lane == 0) sLossW[w] = contrib;
    }
    __syncthreads();

    // ---- deterministic fused finish ----
    if (tid == 0) {
        g_partials[blockIdx.x] = sLossW[0] + sLossW[1] + sLossW[2] + sLossW[3];
        __threadfence();
        const unsigned tk = atomicAdd(&g_ticket, 1u);
        sFlag = (tk == kGrid - 1) ? 1u : 0u;
    }
    __syncthreads();
    if (sFlag) {
        float s = 0.f;
        #pragma unroll
        for (int m = 0; m < kGrid / 256; m++)
            s += __ldcg(&g_partials[tid + m * 256]);   // fixed order
        #pragma unroll
        for (int off = 16; off > 0; off >>= 1)
            s += __shfl_xor_sync(FULL, s, off);
        if (lane == 0) sred[w] = s;
        __syncthreads();
        if (tid == 0) {
            float tot = 0.f;
            #pragma unroll
            for (int i = 0; i < 8; i++) tot += sred[i];
            out[0] = tot * (1.0f / (8.0f * 4096.0f));
            g_ticket = 0u;   // reset for next graph replay
        }
    }
}

extern "C" void kernel_launch(void* const* d_in, const int* in_sizes, int n_in,
                              void* d_out, int out_size) {
    (void)in_sizes; (void)n_in; (void)out_size;
    const float* inp = (const float*)d_in[0];
    cudaFuncSetAttribute(ntxent, cudaFuncAttributeMaxDynamicSharedMemorySize, kSmem);
    ntxent<<<kGrid, 256, kSmem>>>(inp, (float*)d_out);
}

// round 16
// speedup vs baseline: 1.4247x; 1.0967x over previous
#include <cuda_runtime.h>

// NT-Xent loss. inp: (C=8, V=2, B=4096, D=512) fp32.
// Block per 4 b's (256 thr), 3 CTAs/SM. WARP-AUTONOMOUS mainloop over 8
// HALF-B stages (16 rows x 256 floats, 16KB; 2-slot ring = 32KB): warp w
// stages/reads only its 8-chunk slice, cp.async.wait_group + __syncwarp
// only. Per b (2 stages): lane = (g, c8) 8x4 Gram tile accumulated across
// halves, anchors loaded one-at-a-time (regs <= 84 for 3 CTAs/SM),
// 3-stage folded butterfly -> lane owns G[c8][4g+m], ssv allreduce.
// One block barrier, deferred in-warp LSE epilogues, ticket finish.

static constexpr int      kB       = 4096;
static constexpr int      kIter    = 4;
static constexpr int      kGrid    = kB / kIter;        // 1024
static constexpr unsigned FULL     = 0xffffffffu;
static constexpr int      kStageF4 = 16 * 64;           // float4 per half-b stage
static constexpr int      kStageB  = kStageF4 * 16;     // 16 KB
static constexpr int      kRingB   = 2 * kStageB;       // 32 KB
static constexpr int      kPartB   = kIter * 8 * 128 * 4;  // 16 KB
static constexpr int      kOddB    = kIter * 8 * 8 * 4;    // 1 KB
static constexpr int      kSmem    = kRingB + kPartB + kOddB;  // 49 KB

__device__ float    g_partials[kGrid];
__device__ unsigned g_ticket;   // zero-init; reset by last CTA every launch

__device__ __forceinline__ float elem(const float4& v, int d) {
    return d == 0 ? v.x : d == 1 ? v.y : d == 2 ? v.z : v.w;
}

__global__ void __launch_bounds__(256, 3)
ntxent(const float* __restrict__ inp, float* __restrict__ out)
{
    extern __shared__ char dyn[];
    float4* Xs       = reinterpret_cast<float4*>(dyn);                  // [2][16][64]
    float*  sPartAll = reinterpret_cast<float*>(dyn + kRingB);          // [4][8][128]
    float*  sOddAll  = reinterpret_cast<float*>(dyn + kRingB + kPartB); // [4][8][8]
    __shared__ float    snorm[4][16];
    __shared__ float    sLossW[4];
    __shared__ float    sred[8];
    __shared__ unsigned sFlag;

    const int tid  = threadIdx.x;
    const int w    = tid >> 5;
    const int lane = tid & 31;
    const int g    = lane >> 3;         // col quarter: cols [4g, 4g+4)
    const int c8   = lane & 7;          // chunk index within warp slice
    const int chunk = w * 8 + c8;       // chunk within the 64-chunk stage

    // ---- warp-private copy: lane (r4, cc) copies rows 4m+r4, chunk w*8+cc ----
    const int r4 = lane >> 3;           // row residue 0..3
    const int cc = lane & 7;            // chunk within slice
    const long long b0 = (long long)blockIdx.x * kIter;
    // byte addr of (row, b, half, chunk): row*8388608 + b*2048 + half*1024 + chunk*16
    const char* gsrc = (const char*)inp + (size_t)r4 * 8388608 + (size_t)b0 * 2048
                     + (size_t)(w * 8 + cc) * 16;
    const unsigned sdl = (unsigned)__cvta_generic_to_shared(Xs)
                       + r4 * 1024 + (w * 8 + cc) * 16;

    auto issue = [&](int s) {           // s = 2*b_local + half
        const char*    gp = gsrc + (size_t)(s >> 1) * 2048 + (size_t)(s & 1) * 1024;
        const unsigned sp = sdl + (s & 1) * kStageB;
        #pragma unroll
        for (int m = 0; m < 4; m++)     // rows 4m + r4
            asm volatile("cp.async.cg.shared.global [%0], [%1], 16;"
                         :: "r"(sp + m * 4096), "l"(gp + (size_t)m * 33554432));
        asm volatile("cp.async.commit_group;" ::: "memory");
    };

    issue(0);
    issue(1);

    #pragma unroll
    for (int it = 0; it < kIter; it++) {
        float a[32];
        #pragma unroll
        for (int q = 0; q < 32; q++) a[q] = 0.f;
        float ssv[2] = {0.f, 0.f};

        #pragma unroll
        for (int hf = 0; hf < 2; hf++) {
            const int s = it * 2 + hf;
            if (s < 2 * kIter - 1) asm volatile("cp.async.wait_group 1;" ::: "memory");
            else                   asm volatile("cp.async.wait_group 0;" ::: "memory");
            __syncwarp();                     // warp-local: stage visible

            const float4* X = Xs + (s & 1) * kStageF4;

            float4 Cv[4];
            #pragma unroll
            for (int jj = 0; jj < 4; jj++)
                Cv[jj] = X[(4 * g + jj) * 64 + chunk];
            #pragma unroll
            for (int o = 0; o < 2; o++) {     // odd rows 4g+1, 4g+3
                const float4 x = Cv[2 * o + 1];
                float ss = ssv[o];
                ss = fmaf(x.x, x.x, fmaf(x.y, x.y, fmaf(x.z, x.z, fmaf(x.w, x.w, ss))));
                ssv[o] = ss;
            }
            #pragma unroll
            for (int i = 0; i < 8; i++) {     // one anchor at a time (reg cap 84)
                const float4 Av = X[(2 * i) * 64 + chunk];
                #pragma unroll
                for (int d = 0; d < 4; d++) {
                    const float av = elem(Av, d);
                    #pragma unroll
                    for (int jj = 0; jj < 4; jj++)
                        a[i * 4 + jj] = fmaf(av, elem(Cv[jj], d), a[i * 4 + jj]);
                }
            }
            __syncwarp();                     // lanes done reading this slot
            if (s + 2 < 2 * kIter) issue(s + 2);  // slot reused: safe within warp
        }

        // ---- folded butterfly over 8 chunk-lanes (bits 2..0) ----
        #pragma unroll
        for (int st = 0; st < 3; st++) {
            const int  off = 4 >> st;
            const int  n   = 16 >> st;
            const bool hi  = (lane & off) != 0;
            #pragma unroll
            for (int m = 0; m < n; m++) {
                const float mine = hi ? a[m + n] : a[m];
                const float send = hi ? a[m]     : a[m + n];
                a[m] = mine + __shfl_xor_sync(FULL, send, off);
            }
        }
        // lane owns flat32 = 4*c8 + m: i = c8, col = 4g + m
        *reinterpret_cast<float4*>(
            &sPartAll[(it * 8 + w) * 128 + c8 * 16 + 4 * g]) =
            make_float4(a[0], a[1], a[2], a[3]);

        // ---- ssv allreduce over 8 chunk-lanes; writers c8 == 0 ----
        #pragma unroll
        for (int off = 4; off > 0; off >>= 1) {
            ssv[0] += __shfl_xor_sync(FULL, ssv[0], off);
            ssv[1] += __shfl_xor_sync(FULL, ssv[1], off);
        }
        if (c8 == 0) {
            sOddAll[(it * 8 + w) * 8 + 2 * g]     = ssv[0];   // row 4g+1
            sOddAll[(it * 8 + w) * 8 + 2 * g + 1] = ssv[1];   // row 4g+3
        }
    }
    __syncthreads();   // the ONLY block barrier: all warps' partials visible

    // ---- deferred epilogues: warp t handles tile t, fully in-warp ----
    if (w < 4) {
        const int i  = lane >> 2;
        const int kb = 4 * (lane & 3);
        float4 acc = make_float4(0.f, 0.f, 0.f, 0.f);
        #pragma unroll
        for (int ww = 0; ww < 8; ww++) {
            const float4 p = *reinterpret_cast<const float4*>(
                &sPartAll[(w * 8 + ww) * 128 + i * 16 + kb]);
            acc.x += p.x; acc.y += p.y; acc.z += p.z; acc.w += p.w;
        }
        float a4[4] = {acc.x, acc.y, acc.z, acc.w};

        if (lane < 8) {
            float so = 0.f;
            #pragma unroll
            for (int ww = 0; ww < 8; ww++) so += sOddAll[(w * 8 + ww) * 8 + lane];
            snorm[w][2 * lane + 1] = so;
        }
        #pragma unroll
        for (int m = 0; m < 4; m++)                 // even norms = Gram diag
            if (kb + m == 2 * i) snorm[w][2 * i] = a4[m];
        __syncwarp();

        const float inva = 1.0f / fmaxf(sqrtf(snorm[w][2 * i]), 1e-12f);
        float sim[4];
        bool  val[4];
        float mx = -3.0e38f;
        #pragma unroll
        for (int m = 0; m < 4; m++) {
            const int   k    = kb + m;
            const float invk = 1.0f / fmaxf(sqrtf(snorm[w][k]), 1e-12f);
            sim[m] = a4[m] * inva * invk * 10.0f;
            val[m] = ((k >> 1) != i) || (k == 2 * i + 1);
            if (val[m]) mx = fmaxf(mx, sim[m]);
        }
        mx = fmaxf(mx, __shfl_xor_sync(FULL, mx, 1));
        mx = fmaxf(mx, __shfl_xor_sync(FULL, mx, 2));
        float sum = 0.f;
        #pragma unroll
        for (int m = 0; m < 4; m++)
            if (val[m]) sum += __expf(sim[m] - mx);
        sum += __shfl_xor_sync(FULL, sum, 1);
        sum += __shfl_xor_sync(FULL, sum, 2);

        float contrib = 0.f;
        #pragma unroll
        for (int m = 0; m < 4; m++)
            if (kb + m == 2 * i + 1)                // this sim is the positive
                contrib = (mx + __logf(sum)) - sim[m];
        #pragma unroll
        for (int off = 16; off > 0; off >>= 1)
            contrib += __shfl_xor_sync(FULL, contrib, off);
        if (lane == 0) sLossW[w] = contrib;
    }
    __syncthreads();

    // ---- deterministic fused finish ----
    if (tid == 0) {
        g_partials[blockIdx.x] = sLossW[0] + sLossW[1] + sLossW[2] + sLossW[3];
        __threadfence();
        const unsigned tk = atomicAdd(&g_ticket, 1u);
        sFlag = (tk == kGrid - 1) ? 1u : 0u;
    }
    __syncthreads();
    if (sFlag) {
        float s = 0.f;
        #pragma unroll
        for (int m = 0; m < kGrid / 256; m++)
            s += __ldcg(&g_partials[tid + m * 256]);   // fixed order
        #pragma unroll
        for (int off = 16; off > 0; off >>= 1)
            s += __shfl_xor_sync(FULL, s, off);
        if (lane == 0) sred[w] = s;
        __syncthreads();
        if (tid == 0) {
            float tot = 0.f;
            #pragma unroll
            for (int i = 0; i < 8; i++) tot += sred[i];
            out[0] = tot * (1.0f / (8.0f * 4096.0f));
            g_ticket = 0u;   // reset for next graph replay
        }
    }
}

extern "C" void kernel_launch(void* const* d_in, const int* in_sizes, int n_in,
                              void* d_out, int out_size) {
    (void)in_sizes; (void)n_in; (void)out_size;
    const float* inp = (const float*)d_in[0];
    cudaFuncSetAttribute(ntxent, cudaFuncAttributeMaxDynamicSharedMemorySize, kSmem);
    ntxent<<<kGrid, 256, kSmem>>>(inp, (float*)d_out);
}